// round 1
// baseline (speedup 1.0000x reference)
#include <cuda_runtime.h>
#include <cuda_bf16.h>

// Inputs (metadata order):
//   d_in[0] = x            float32 [65536]
//   d_in[1] = edge_weights float32 [16777216]
//   d_in[2] = bias         float32 [65536]
//   d_in[3] = src          int32   [16777216]
//   d_in[4] = dst          int32   [16777216]
// Output: float32 [65536],  out[i] = bias[i] + sum_{e: dst[e]==i} x[src[e]]*edge_weights[e]

__global__ void init_out_kernel(const float* __restrict__ bias,
                                float* __restrict__ out, int n) {
    int i = blockIdx.x * blockDim.x + threadIdx.x;
    if (i < n) out[i] = bias[i];
}

__global__ void scatter_kernel(const float* __restrict__ x,
                               const float* __restrict__ ew,
                               const int*   __restrict__ src,
                               const int*   __restrict__ dst,
                               float* __restrict__ out,
                               int n) {
    const int n4 = n >> 2;
    const float4* __restrict__ ew4 = reinterpret_cast<const float4*>(ew);
    const int4*   __restrict__ s4  = reinterpret_cast<const int4*>(src);
    const int4*   __restrict__ d4  = reinterpret_cast<const int4*>(dst);

    const int stride = gridDim.x * blockDim.x;
    for (int i = blockIdx.x * blockDim.x + threadIdx.x; i < n4; i += stride) {
        float4 w = ew4[i];
        int4   s = s4[i];
        int4   d = d4[i];

        // Gather all four x values first (MLP=4 hides L2 latency),
        // then fire the reductions.
        float xa = __ldg(&x[s.x]);
        float xb = __ldg(&x[s.y]);
        float xc = __ldg(&x[s.z]);
        float xd = __ldg(&x[s.w]);

        atomicAdd(&out[d.x], w.x * xa);
        atomicAdd(&out[d.y], w.y * xb);
        atomicAdd(&out[d.z], w.z * xc);
        atomicAdd(&out[d.w], w.w * xd);
    }

    // Tail (n not divisible by 4) — at most 3 elements.
    int tail_start = n4 << 2;
    int t = blockIdx.x * blockDim.x + threadIdx.x;
    if (t < n - tail_start) {
        int e = tail_start + t;
        atomicAdd(&out[dst[e]], ew[e] * __ldg(&x[e < n ? src[e] : 0]));
    }
}

extern "C" void kernel_launch(void* const* d_in, const int* in_sizes, int n_in,
                              void* d_out, int out_size) {
    const float* x    = (const float*)d_in[0];
    const float* ew   = (const float*)d_in[1];
    const float* bias = (const float*)d_in[2];
    const int*   src  = (const int*)d_in[3];
    const int*   dst  = (const int*)d_in[4];
    float* out = (float*)d_out;

    const int n_nodes = in_sizes[0];
    const int n_edges = in_sizes[1];

    // 1) out = bias
    {
        int threads = 256;
        int blocks  = (n_nodes + threads - 1) / threads;
        init_out_kernel<<<blocks, threads>>>(bias, out, n_nodes);
    }

    // 2) scatter-add over edges
    {
        int threads = 256;
        // full-chip occupancy: 148 SMs * up to ~8 CTAs of 256; grid-stride covers all.
        int blocks = 2048;
        int n4 = n_edges >> 2;
        int max_blocks = (n4 + threads - 1) / threads;
        if (blocks > max_blocks) blocks = max_blocks;
        if (blocks < 1) blocks = 1;
        scatter_kernel<<<blocks, threads>>>(x, ew, src, dst, out, n_edges);
    }
}